// round 1
// baseline (speedup 1.0000x reference)
#include <cuda_runtime.h>
#include <math.h>
#include <stdint.h>

#define NCELLS 10000
#define EDGES  320000
#define HID    256

// ---------------- scratch (static device globals; no allocation allowed) ----
__device__ float g_h[2 * 2 * NCELLS * HID];        // h per (modality, order)
__device__ float g_acc[2 * NCELLS * 2 * HID];      // concat accumulators per modality [N,512]
__device__ float g_x[2 * NCELLS * HID];            // ping-pong propagation buffers
__device__ float g_t1[NCELLS * HID];               // decoder hidden
__device__ int   g_rowptr[2 * (NCELLS + 1)];
__device__ int   g_cnt[2 * NCELLS];
__device__ int   g_woff[2 * NCELLS];
__device__ int   g_ccol[2 * EDGES];
__device__ float g_cval[2 * EDGES];
__device__ float g_fw[4 * 11];                     // softmaxed propagation weights

// ---------------- small utility kernels ------------------------------------
__global__ void zero_int_kernel(int* p, int n) {
    int i = blockIdx.x * blockDim.x + threadIdx.x;
    if (i < n) p[i] = 0;
}

__global__ void hist_kernel(const int* __restrict__ row, int e, int* cnt) {
    int i = blockIdx.x * blockDim.x + threadIdx.x;
    if (i < e) atomicAdd(&cnt[row[i]], 1);
}

// single-block chunked Hillis-Steele scan: rowptr[0]=0, rowptr[i+1]=sum cnt[0..i]
__global__ void scan_kernel(const int* __restrict__ cnt, int* rowptr, int n) {
    __shared__ int buf[1024];
    __shared__ int carry;
    if (threadIdx.x == 0) { carry = 0; rowptr[0] = 0; }
    __syncthreads();
    for (int base = 0; base < n; base += 1024) {
        int i = base + threadIdx.x;
        int v = (i < n) ? cnt[i] : 0;
        buf[threadIdx.x] = v;
        __syncthreads();
        for (int off = 1; off < 1024; off <<= 1) {
            int t = 0;
            if (threadIdx.x >= off) t = buf[threadIdx.x - off];
            __syncthreads();
            if (threadIdx.x >= off) buf[threadIdx.x] += t;
            __syncthreads();
        }
        if (i < n) rowptr[i + 1] = carry + buf[threadIdx.x];
        __syncthreads();
        if (threadIdx.x == 0) carry += buf[1023];
        __syncthreads();
    }
}

__global__ void copy_int_kernel(const int* __restrict__ a, int* b, int n) {
    int i = blockIdx.x * blockDim.x + threadIdx.x;
    if (i < n) b[i] = a[i];
}

__global__ void scatter_kernel(const int* __restrict__ row, const int* __restrict__ col,
                               const float* __restrict__ val, int e,
                               int* woff, int* ccol, float* cval) {
    int i = blockIdx.x * blockDim.x + threadIdx.x;
    if (i < e) {
        int r = row[i];
        int p = atomicAdd(&woff[r], 1);
        ccol[p] = col[i];
        cval[p] = val[i];
    }
}

// softmax of the 4 chains' [11] propagation-weight logits
__global__ void softmax_fw_kernel(const float* __restrict__ fW_rna,
                                  const float* __restrict__ fW_atac,
                                  float* __restrict__ fw_out) {
    int id = threadIdx.x;
    if (id >= 4) return;
    const float* src = (id < 2) ? (fW_rna + id * 11) : (fW_atac + (id - 2) * 11);
    float m = -1e30f;
    for (int k = 0; k < 11; k++) m = fmaxf(m, src[k]);
    float e[11], s = 0.f;
    for (int k = 0; k < 11; k++) { e[k] = expf(src[k] - m); s += e[k]; }
    float inv = 1.f / s;
    for (int k = 0; k < 11; k++) fw_out[id * 11 + k] = e[k] * inv;
}

// acc = fw0 * h
__global__ void init_acc_kernel(const float* __restrict__ h, float* __restrict__ acc,
                                int accLd, const float* __restrict__ wptr) {
    int n = blockIdx.x, t = threadIdx.x;
    acc[(size_t)n * accLd + t] = wptr[0] * h[(size_t)n * HID + t];
}

// CSR spmm: y[r,:] = sum_e val[e] * x[col[e],:], plus acc += w * y
__global__ void spmm_csr_kernel(const int* __restrict__ rowptr,
                                const int* __restrict__ cols,
                                const float* __restrict__ vals,
                                const float* __restrict__ x,
                                float* __restrict__ y,
                                float* __restrict__ acc, int accLd,
                                const float* __restrict__ wptr) {
    int r = blockIdx.x;
    int t = threadIdx.x;
    int s = rowptr[r], e = rowptr[r + 1];
    float sum = 0.f;
    int i = s;
    // 2-deep software pipeline over the edge metadata to cover L2 latency a bit
    for (; i + 1 < e; i += 2) {
        int   c0 = __ldg(&cols[i]);
        int   c1 = __ldg(&cols[i + 1]);
        float v0 = __ldg(&vals[i]);
        float v1 = __ldg(&vals[i + 1]);
        float x0 = __ldg(&x[(size_t)c0 * HID + t]);
        float x1 = __ldg(&x[(size_t)c1 * HID + t]);
        sum += v0 * x0;
        sum += v1 * x1;
    }
    if (i < e) {
        int c = __ldg(&cols[i]);
        sum += __ldg(&vals[i]) * __ldg(&x[(size_t)c * HID + t]);
    }
    y[(size_t)r * HID + t] = sum;
    acc[(size_t)r * accLd + t] += __ldg(wptr) * sum;
}

// attention fusion: weight = softmax([z_rna z_atac] @ Wa + ba); z = w0*z_rna + w1*z_atac
__global__ void fuse_kernel(const float* __restrict__ z_rna, const float* __restrict__ z_atac,
                            const float* __restrict__ Wa, const float* __restrict__ ba,
                            float* __restrict__ z, float* __restrict__ weight) {
    int n = blockIdx.x, t = threadIdx.x;
    float zr = z_rna[(size_t)n * HID + t];
    float za = z_atac[(size_t)n * HID + t];
    float p0 = zr * Wa[t * 2 + 0] + za * Wa[(HID + t) * 2 + 0];
    float p1 = zr * Wa[t * 2 + 1] + za * Wa[(HID + t) * 2 + 1];
    __shared__ float s0[256], s1[256];
    s0[t] = p0; s1[t] = p1;
    __syncthreads();
    for (int off = 128; off > 0; off >>= 1) {
        if (t < off) { s0[t] += s0[t + off]; s1[t] += s1[t + off]; }
        __syncthreads();
    }
    __shared__ float w0s, w1s;
    if (t == 0) {
        float a0 = s0[0] + ba[0];
        float a1 = s1[0] + ba[1];
        float m = fmaxf(a0, a1);
        float e0 = expf(a0 - m), e1 = expf(a1 - m);
        float inv = 1.f / (e0 + e1);
        w0s = e0 * inv; w1s = e1 * inv;
        weight[n * 2 + 0] = w0s;
        weight[n * 2 + 1] = w1s;
    }
    __syncthreads();
    z[(size_t)n * HID + t] = w0s * zr + w1s * za;
}

// ---------------- SGEMM: C = A @ B + bias (optional relu) ------------------
// 128x128 block tile, BK=8, 256 threads, 8x8 per thread. K must be %8, all
// row strides %4 (true for every GEMM here). M/N edges guarded.
__global__ __launch_bounds__(256, 2)
void sgemm_kernel(int M, int N, int K,
                  const float* __restrict__ A, int lda,
                  const float* __restrict__ B, int ldb,
                  const float* __restrict__ bias,
                  float* __restrict__ C, int ldc,
                  int relu) {
    __shared__ float As[8][128];
    __shared__ float Bs[8][128];
    const int tid = threadIdx.x;
    const int tx = tid & 15;
    const int ty = tid >> 4;
    const int mBase = blockIdx.y * 128;
    const int nBase = blockIdx.x * 128;

    const int aRow = tid >> 1;
    const int aCol = (tid & 1) << 2;
    const int bRow = tid >> 5;
    const int bCol = (tid & 31) << 2;

    float acc[8][8];
#pragma unroll
    for (int i = 0; i < 8; i++)
#pragma unroll
        for (int j = 0; j < 8; j++) acc[i][j] = 0.f;

    const int  gmA    = mBase + aRow;
    const bool aValid = (gmA < M);
    const float* Aptr = A + (size_t)gmA * lda + aCol;
    const int   gnB   = nBase + bCol;

    for (int k0 = 0; k0 < K; k0 += 8) {
        float4 av = make_float4(0.f, 0.f, 0.f, 0.f);
        if (aValid) av = *(const float4*)(Aptr + k0);
        As[aCol + 0][aRow] = av.x;
        As[aCol + 1][aRow] = av.y;
        As[aCol + 2][aRow] = av.z;
        As[aCol + 3][aRow] = av.w;

        float4 bv = make_float4(0.f, 0.f, 0.f, 0.f);
        const float* bp = B + (size_t)(k0 + bRow) * ldb;
        if (gnB + 3 < N) {
            bv = *(const float4*)(bp + gnB);
        } else if (gnB < N) {
            float tmp[4] = {0.f, 0.f, 0.f, 0.f};
            for (int q = 0; q < 4; q++)
                if (gnB + q < N) tmp[q] = bp[gnB + q];
            bv = make_float4(tmp[0], tmp[1], tmp[2], tmp[3]);
        }
        *(float4*)&Bs[bRow][bCol] = bv;
        __syncthreads();

#pragma unroll
        for (int k = 0; k < 8; k++) {
            float4 a0 = *(const float4*)&As[k][ty * 8];
            float4 a1 = *(const float4*)&As[k][ty * 8 + 4];
            float4 b0 = *(const float4*)&Bs[k][tx * 8];
            float4 b1 = *(const float4*)&Bs[k][tx * 8 + 4];
            float ar[8] = {a0.x, a0.y, a0.z, a0.w, a1.x, a1.y, a1.z, a1.w};
            float br[8] = {b0.x, b0.y, b0.z, b0.w, b1.x, b1.y, b1.z, b1.w};
#pragma unroll
            for (int i = 0; i < 8; i++)
#pragma unroll
                for (int j = 0; j < 8; j++) acc[i][j] += ar[i] * br[j];
        }
        __syncthreads();
    }

#pragma unroll
    for (int i = 0; i < 8; i++) {
        int gm = mBase + ty * 8 + i;
        if (gm >= M) continue;
        float* crow = C + (size_t)gm * ldc;
#pragma unroll
        for (int j = 0; j < 8; j++) {
            int gn = nBase + tx * 8 + j;
            if (gn < N) {
                float v = acc[i][j] + bias[gn];
                if (relu) v = fmaxf(v, 0.f);
                crow[gn] = v;
            }
        }
    }
}

// ---------------- host side -------------------------------------------------
static inline void launch_gemm(int M, int N, int K,
                               const float* A, int lda,
                               const float* B, int ldb,
                               const float* bias,
                               float* C, int ldc, int relu) {
    dim3 grid((N + 127) / 128, (M + 127) / 128);
    sgemm_kernel<<<grid, 256>>>(M, N, K, A, lda, B, ldb, bias, C, ldc, relu);
}

extern "C" void kernel_launch(void* const* d_in, const int* in_sizes, int n_in,
                              void* d_out, int out_size) {
    (void)n_in; (void)out_size;
    const float* X[2]   = {(const float*)d_in[0], (const float*)d_in[1]};
    const int*   row[2] = {(const int*)d_in[2], (const int*)d_in[5]};
    const int*   col[2] = {(const int*)d_in[3], (const int*)d_in[6]};
    const float* val[2] = {(const float*)d_in[4], (const float*)d_in[7]};
    const float* Wi[2]  = {(const float*)d_in[8],  (const float*)d_in[13]};
    const float* bi[2]  = {(const float*)d_in[9],  (const float*)d_in[14]};
    const float* fWl[2] = {(const float*)d_in[10], (const float*)d_in[15]};
    const float* Wo[2]  = {(const float*)d_in[11], (const float*)d_in[16]};
    const float* bo[2]  = {(const float*)d_in[12], (const float*)d_in[17]};
    const float* Wa     = (const float*)d_in[18];
    const float* ba     = (const float*)d_in[19];
    const float* Wd1[2] = {(const float*)d_in[20], (const float*)d_in[24]};
    const float* bd1[2] = {(const float*)d_in[21], (const float*)d_in[25]};
    const float* Wd2[2] = {(const float*)d_in[22], (const float*)d_in[26]};
    const float* bd2[2] = {(const float*)d_in[23], (const float*)d_in[27]};
    const int D[2] = {2000, 5000};
    const int E = in_sizes[2];

    float* out = (float*)d_out;
    float* z_out       = out;
    float* zmod_out[2] = {out + (size_t)NCELLS * HID, out + 2 * (size_t)NCELLS * HID};
    float* w_out       = out + 3 * (size_t)NCELLS * HID;
    float* rec_out[2];
    rec_out[0] = w_out + (size_t)NCELLS * 2;
    rec_out[1] = rec_out[0] + (size_t)NCELLS * 2000;

    // scratch pointers
    float *hb, *accb, *xb, *t1b, *cvb, *fwb;
    int *rpb, *cntb, *wob, *ccb;
    cudaGetSymbolAddress((void**)&hb,   g_h);
    cudaGetSymbolAddress((void**)&accb, g_acc);
    cudaGetSymbolAddress((void**)&xb,   g_x);
    cudaGetSymbolAddress((void**)&t1b,  g_t1);
    cudaGetSymbolAddress((void**)&rpb,  g_rowptr);
    cudaGetSymbolAddress((void**)&cntb, g_cnt);
    cudaGetSymbolAddress((void**)&wob,  g_woff);
    cudaGetSymbolAddress((void**)&ccb,  g_ccol);
    cudaGetSymbolAddress((void**)&cvb,  g_cval);
    cudaGetSymbolAddress((void**)&fwb,  g_fw);

    // ---- CSR build for both hypergraph orders ----
    zero_int_kernel<<<(2 * NCELLS + 255) / 256, 256>>>(cntb, 2 * NCELLS);
    for (int o = 0; o < 2; o++) {
        int* cnt  = cntb + o * NCELLS;
        int* rp   = rpb + o * (NCELLS + 1);
        int* wo   = wob + o * NCELLS;
        int* cc   = ccb + o * EDGES;
        float* cv = cvb + o * EDGES;
        hist_kernel<<<(E + 255) / 256, 256>>>(row[o], E, cnt);
        scan_kernel<<<1, 1024>>>(cnt, rp, NCELLS);
        copy_int_kernel<<<(NCELLS + 255) / 256, 256>>>(rp, wo, NCELLS);
        scatter_kernel<<<(E + 255) / 256, 256>>>(row[o], col[o], val[o], E, wo, cc, cv);
    }
    softmax_fw_kernel<<<1, 32>>>(fWl[0], fWl[1], fwb);

    // ---- input projections: h[m][o] = X[m] @ Wi[m][o] + bi[m][o] ----
    for (int m = 0; m < 2; m++)
        for (int o = 0; o < 2; o++) {
            float* h = hb + (size_t)(m * 2 + o) * NCELLS * HID;
            launch_gemm(NCELLS, HID, D[m], X[m], D[m],
                        Wi[m] + (size_t)o * D[m] * HID, HID,
                        bi[m] + o * HID, h, HID, 0);
        }

    // ---- K-hop propagation per (modality, order) chain ----
    for (int m = 0; m < 2; m++)
        for (int o = 0; o < 2; o++) {
            const float* h  = hb + (size_t)(m * 2 + o) * NCELLS * HID;
            float* accp     = accb + (size_t)m * NCELLS * 2 * HID + o * HID;
            const float* fw = fwb + (m * 2 + o) * 11;
            const int* rp   = rpb + o * (NCELLS + 1);
            const int* cc   = ccb + o * EDGES;
            const float* cv = cvb + o * EDGES;

            init_acc_kernel<<<NCELLS, 256>>>(h, accp, 2 * HID, fw);
            const float* xc = h;
            float* xa = xb;
            float* xo2 = xb + (size_t)NCELLS * HID;
            for (int k = 1; k <= 10; k++) {
                spmm_csr_kernel<<<NCELLS, 256>>>(rp, cc, cv, xc, xa, accp, 2 * HID, fw + k);
                xc = xa;
                float* tmp = xa; xa = xo2; xo2 = tmp;
            }
        }

    // ---- output mixes: z_mod = acc @ Wo + bo (written straight into d_out) ----
    for (int m = 0; m < 2; m++) {
        const float* accp = accb + (size_t)m * NCELLS * 2 * HID;
        launch_gemm(NCELLS, HID, 2 * HID, accp, 2 * HID, Wo[m], HID, bo[m],
                    zmod_out[m], HID, 0);
    }

    // ---- attention fusion ----
    fuse_kernel<<<NCELLS, 256>>>(zmod_out[0], zmod_out[1], Wa, ba, z_out, w_out);

    // ---- decoders ----
    for (int m = 0; m < 2; m++) {
        launch_gemm(NCELLS, HID, HID, z_out, HID, Wd1[m], HID, bd1[m], t1b, HID, 1);
        launch_gemm(NCELLS, D[m], HID, t1b, HID, Wd2[m], D[m], bd2[m], rec_out[m], D[m], 0);
    }
}

// round 2
// speedup vs baseline: 2.1047x; 2.1047x over previous
#include <cuda_runtime.h>
#include <math.h>
#include <stdint.h>

#define NCELLS 10000
#define EDGES  320000
#define HID    256

// ---------------- scratch (static device globals; no allocation allowed) ----
__device__ float g_h[2 * 2 * NCELLS * HID];        // h per (modality, order)
__device__ float g_acc[2 * NCELLS * 2 * HID];      // concat accumulators per modality [N,512]
__device__ float g_x[2 * NCELLS * HID];            // ping-pong propagation buffers
__device__ float g_t1[NCELLS * HID];               // decoder hidden
__device__ int   g_rowptr[2 * (NCELLS + 1)];
__device__ int   g_cnt[2 * NCELLS];
__device__ int   g_woff[2 * NCELLS];
__device__ int   g_ccol[2 * EDGES];
__device__ float g_cval[2 * EDGES];
__device__ float g_fw[4 * 11];                     // softmaxed propagation weights

// ---------------- small utility kernels ------------------------------------
__global__ void zero_int_kernel(int* p, int n) {
    int i = blockIdx.x * blockDim.x + threadIdx.x;
    if (i < n) p[i] = 0;
}

__global__ void hist_kernel(const int* __restrict__ row, int e, int* cnt) {
    int i = blockIdx.x * blockDim.x + threadIdx.x;
    if (i < e) atomicAdd(&cnt[row[i]], 1);
}

// single-block chunked Hillis-Steele scan: rowptr[0]=0, rowptr[i+1]=sum cnt[0..i]
__global__ void scan_kernel(const int* __restrict__ cnt, int* rowptr, int n) {
    __shared__ int buf[1024];
    __shared__ int carry;
    if (threadIdx.x == 0) { carry = 0; rowptr[0] = 0; }
    __syncthreads();
    for (int base = 0; base < n; base += 1024) {
        int i = base + threadIdx.x;
        int v = (i < n) ? cnt[i] : 0;
        buf[threadIdx.x] = v;
        __syncthreads();
        for (int off = 1; off < 1024; off <<= 1) {
            int t = 0;
            if (threadIdx.x >= off) t = buf[threadIdx.x - off];
            __syncthreads();
            if (threadIdx.x >= off) buf[threadIdx.x] += t;
            __syncthreads();
        }
        if (i < n) rowptr[i + 1] = carry + buf[threadIdx.x];
        __syncthreads();
        if (threadIdx.x == 0) carry += buf[1023];
        __syncthreads();
    }
}

__global__ void copy_int_kernel(const int* __restrict__ a, int* b, int n) {
    int i = blockIdx.x * blockDim.x + threadIdx.x;
    if (i < n) b[i] = a[i];
}

__global__ void scatter_kernel(const int* __restrict__ row, const int* __restrict__ col,
                               const float* __restrict__ val, int e,
                               int* woff, int* ccol, float* cval) {
    int i = blockIdx.x * blockDim.x + threadIdx.x;
    if (i < e) {
        int r = row[i];
        int p = atomicAdd(&woff[r], 1);
        ccol[p] = col[i];
        cval[p] = val[i];
    }
}

// softmax of the 4 chains' [11] propagation-weight logits
__global__ void softmax_fw_kernel(const float* __restrict__ fW_rna,
                                  const float* __restrict__ fW_atac,
                                  float* __restrict__ fw_out) {
    int id = threadIdx.x;
    if (id >= 4) return;
    const float* src = (id < 2) ? (fW_rna + id * 11) : (fW_atac + (id - 2) * 11);
    float m = -1e30f;
    for (int k = 0; k < 11; k++) m = fmaxf(m, src[k]);
    float e[11], s = 0.f;
    for (int k = 0; k < 11; k++) { e[k] = expf(src[k] - m); s += e[k]; }
    float inv = 1.f / s;
    for (int k = 0; k < 11; k++) fw_out[id * 11 + k] = e[k] * inv;
}

// acc = fw0 * h
__global__ void init_acc_kernel(const float* __restrict__ h, float* __restrict__ acc,
                                int accLd, const float* __restrict__ wptr) {
    int n = blockIdx.x, t = threadIdx.x;
    acc[(size_t)n * accLd + t] = wptr[0] * h[(size_t)n * HID + t];
}

// CSR spmm: y[r,:] = sum_e val[e] * x[col[e],:], plus acc += w * y
__global__ void spmm_csr_kernel(const int* __restrict__ rowptr,
                                const int* __restrict__ cols,
                                const float* __restrict__ vals,
                                const float* __restrict__ x,
                                float* __restrict__ y,
                                float* __restrict__ acc, int accLd,
                                const float* __restrict__ wptr) {
    int r = blockIdx.x;
    int t = threadIdx.x;
    int s = rowptr[r], e = rowptr[r + 1];
    float sum = 0.f;
    int i = s;
    for (; i + 1 < e; i += 2) {
        int   c0 = __ldg(&cols[i]);
        int   c1 = __ldg(&cols[i + 1]);
        float v0 = __ldg(&vals[i]);
        float v1 = __ldg(&vals[i + 1]);
        float x0 = __ldg(&x[(size_t)c0 * HID + t]);
        float x1 = __ldg(&x[(size_t)c1 * HID + t]);
        sum += v0 * x0;
        sum += v1 * x1;
    }
    if (i < e) {
        int c = __ldg(&cols[i]);
        sum += __ldg(&vals[i]) * __ldg(&x[(size_t)c * HID + t]);
    }
    y[(size_t)r * HID + t] = sum;
    acc[(size_t)r * accLd + t] += __ldg(wptr) * sum;
}

// attention fusion: weight = softmax([z_rna z_atac] @ Wa + ba); z = w0*z_rna + w1*z_atac
__global__ void fuse_kernel(const float* __restrict__ z_rna, const float* __restrict__ z_atac,
                            const float* __restrict__ Wa, const float* __restrict__ ba,
                            float* __restrict__ z, float* __restrict__ weight) {
    int n = blockIdx.x, t = threadIdx.x;
    float zr = z_rna[(size_t)n * HID + t];
    float za = z_atac[(size_t)n * HID + t];
    float p0 = zr * Wa[t * 2 + 0] + za * Wa[(HID + t) * 2 + 0];
    float p1 = zr * Wa[t * 2 + 1] + za * Wa[(HID + t) * 2 + 1];
    __shared__ float s0[256], s1[256];
    s0[t] = p0; s1[t] = p1;
    __syncthreads();
    for (int off = 128; off > 0; off >>= 1) {
        if (t < off) { s0[t] += s0[t + off]; s1[t] += s1[t + off]; }
        __syncthreads();
    }
    __shared__ float w0s, w1s;
    if (t == 0) {
        float a0 = s0[0] + ba[0];
        float a1 = s1[0] + ba[1];
        float m = fmaxf(a0, a1);
        float e0 = expf(a0 - m), e1 = expf(a1 - m);
        float inv = 1.f / (e0 + e1);
        w0s = e0 * inv; w1s = e1 * inv;
        weight[n * 2 + 0] = w0s;
        weight[n * 2 + 1] = w1s;
    }
    __syncthreads();
    z[(size_t)n * HID + t] = w0s * zr + w1s * za;
}

// ---------------- TF32 tensor-core GEMM -------------------------------------
// C = A[MxK] @ B[KxN] + bias (optional relu). 128x128 block tile, BK=16,
// 256 threads = 8 warps in 2x4, warp tile 64x32 via mma.m16n8k8.tf32.
// cp.async double-buffered. K remainder and M/N edges zero-filled/guarded.

__device__ __forceinline__ uint32_t f2tf32(float x) {
    uint32_t r;
    asm("cvt.rna.tf32.f32 %0, %1;" : "=r"(r) : "f"(x));
    return r;
}

__device__ __forceinline__ void mma_tf32(float* d, const uint32_t* a, const uint32_t* b) {
    asm volatile(
        "mma.sync.aligned.m16n8k8.row.col.f32.tf32.tf32.f32 "
        "{%0,%1,%2,%3}, {%4,%5,%6,%7}, {%8,%9}, {%0,%1,%2,%3};"
        : "+f"(d[0]), "+f"(d[1]), "+f"(d[2]), "+f"(d[3])
        : "r"(a[0]), "r"(a[1]), "r"(a[2]), "r"(a[3]), "r"(b[0]), "r"(b[1]));
}

__device__ __forceinline__ void cpasync16(uint32_t dst, const void* src, int srcBytes) {
    asm volatile("cp.async.ca.shared.global [%0], [%1], 16, %2;"
                 :: "r"(dst), "l"(src), "r"(srcBytes));
}

__global__ __launch_bounds__(256, 2)
void tf32_gemm_kernel(int M, int N, int K,
                      const float* __restrict__ A, int lda,
                      const float* __restrict__ B, int ldb,
                      const float* __restrict__ bias,
                      float* __restrict__ C, int ldc, int relu) {
    __shared__ float As[2][128][20];   // [m][k], pad 4 -> conflict-free frag loads
    __shared__ float Bs[2][16][136];   // [k][n], pad 8 -> conflict-free frag loads

    const int tid  = threadIdx.x;
    const int wid  = tid >> 5;
    const int lane = tid & 31;
    const int wm   = (wid >> 2) * 64;   // warp m offset (2 rows of warps)
    const int wn   = (wid & 3) * 32;    // warp n offset (4 cols of warps)
    const int r    = lane >> 2;         // 0..7
    const int c    = lane & 3;          // 0..3
    const int mBase = blockIdx.y * 128;
    const int nBase = blockIdx.x * 128;

    float acc[4][4][4];
#pragma unroll
    for (int i = 0; i < 4; i++)
#pragma unroll
        for (int j = 0; j < 4; j++)
#pragma unroll
            for (int q = 0; q < 4; q++) acc[i][j][q] = 0.f;

    const int NT = (K + 15) / 16;

    // stage loader: A tile 128x16 (512 float4), B tile 16x128 (512 float4)
    auto load_stage = [&](int st, int k0) {
#pragma unroll
        for (int i = 0; i < 2; i++) {
            int ch = tid + i * 256;
            int m  = ch >> 2;
            int k4 = (ch & 3) << 2;
            const float* src = A + (size_t)(mBase + m) * lda + (k0 + k4);
            int sz = ((mBase + m) < M && (k0 + k4) < K) ? 16 : 0;
            cpasync16((uint32_t)__cvta_generic_to_shared(&As[st][m][k4]), src, sz);
        }
#pragma unroll
        for (int i = 0; i < 2; i++) {
            int ch = tid + i * 256;
            int k  = ch >> 5;
            int nc = (ch & 31) << 2;
            const float* src = B + (size_t)(k0 + k) * ldb + (nBase + nc);
            int sz = ((k0 + k) < K && (nBase + nc) < N) ? 16 : 0;
            cpasync16((uint32_t)__cvta_generic_to_shared(&Bs[st][k][nc]), src, sz);
        }
        asm volatile("cp.async.commit_group;");
    };

    load_stage(0, 0);

    for (int t = 0; t < NT; ++t) {
        int st = t & 1;
        if (t + 1 < NT) {
            load_stage(st ^ 1, (t + 1) * 16);
            asm volatile("cp.async.wait_group 1;");
        } else {
            asm volatile("cp.async.wait_group 0;");
        }
        __syncthreads();

#pragma unroll
        for (int s = 0; s < 2; ++s) {
            const int kk = s * 8;
            uint32_t af[4][4], bf[4][2];
#pragma unroll
            for (int mt = 0; mt < 4; mt++) {
                int m = wm + mt * 16;
                af[mt][0] = f2tf32(As[st][m + r    ][kk + c    ]);
                af[mt][1] = f2tf32(As[st][m + r + 8][kk + c    ]);
                af[mt][2] = f2tf32(As[st][m + r    ][kk + c + 4]);
                af[mt][3] = f2tf32(As[st][m + r + 8][kk + c + 4]);
            }
#pragma unroll
            for (int nt = 0; nt < 4; nt++) {
                int n = wn + nt * 8;
                bf[nt][0] = f2tf32(Bs[st][kk + c    ][n + r]);
                bf[nt][1] = f2tf32(Bs[st][kk + c + 4][n + r]);
            }
#pragma unroll
            for (int mt = 0; mt < 4; mt++)
#pragma unroll
                for (int nt = 0; nt < 4; nt++)
                    mma_tf32(acc[mt][nt], af[mt], bf[nt]);
        }
        __syncthreads();
    }

    // epilogue: bias (+relu), float2 stores
#pragma unroll
    for (int mt = 0; mt < 4; mt++) {
        int row0 = mBase + wm + mt * 16 + r;
#pragma unroll
        for (int nt = 0; nt < 4; nt++) {
            int col = nBase + wn + nt * 8 + 2 * c;
            if (col < N) {
                float b0v = bias[col], b1v = bias[col + 1];
                if (row0 < M) {
                    float v0 = acc[mt][nt][0] + b0v;
                    float v1 = acc[mt][nt][1] + b1v;
                    if (relu) { v0 = fmaxf(v0, 0.f); v1 = fmaxf(v1, 0.f); }
                    *(float2*)&C[(size_t)row0 * ldc + col] = make_float2(v0, v1);
                }
                int row1 = row0 + 8;
                if (row1 < M) {
                    float v0 = acc[mt][nt][2] + b0v;
                    float v1 = acc[mt][nt][3] + b1v;
                    if (relu) { v0 = fmaxf(v0, 0.f); v1 = fmaxf(v1, 0.f); }
                    *(float2*)&C[(size_t)row1 * ldc + col] = make_float2(v0, v1);
                }
            }
        }
    }
}

// ---------------- host side -------------------------------------------------
static inline void launch_gemm(int M, int N, int K,
                               const float* A, int lda,
                               const float* B, int ldb,
                               const float* bias,
                               float* C, int ldc, int relu) {
    dim3 grid((N + 127) / 128, (M + 127) / 128);
    tf32_gemm_kernel<<<grid, 256>>>(M, N, K, A, lda, B, ldb, bias, C, ldc, relu);
}

extern "C" void kernel_launch(void* const* d_in, const int* in_sizes, int n_in,
                              void* d_out, int out_size) {
    (void)n_in; (void)out_size;
    const float* X[2]   = {(const float*)d_in[0], (const float*)d_in[1]};
    const int*   row[2] = {(const int*)d_in[2], (const int*)d_in[5]};
    const int*   col[2] = {(const int*)d_in[3], (const int*)d_in[6]};
    const float* val[2] = {(const float*)d_in[4], (const float*)d_in[7]};
    const float* Wi[2]  = {(const float*)d_in[8],  (const float*)d_in[13]};
    const float* bi[2]  = {(const float*)d_in[9],  (const float*)d_in[14]};
    const float* fWl[2] = {(const float*)d_in[10], (const float*)d_in[15]};
    const float* Wo[2]  = {(const float*)d_in[11], (const float*)d_in[16]};
    const float* bo[2]  = {(const float*)d_in[12], (const float*)d_in[17]};
    const float* Wa     = (const float*)d_in[18];
    const float* ba     = (const float*)d_in[19];
    const float* Wd1[2] = {(const float*)d_in[20], (const float*)d_in[24]};
    const float* bd1[2] = {(const float*)d_in[21], (const float*)d_in[25]};
    const float* Wd2[2] = {(const float*)d_in[22], (const float*)d_in[26]};
    const float* bd2[2] = {(const float*)d_in[23], (const float*)d_in[27]};
    const int D[2] = {2000, 5000};
    const int E = in_sizes[2];

    float* out = (float*)d_out;
    float* z_out       = out;
    float* zmod_out[2] = {out + (size_t)NCELLS * HID, out + 2 * (size_t)NCELLS * HID};
    float* w_out       = out + 3 * (size_t)NCELLS * HID;
    float* rec_out[2];
    rec_out[0] = w_out + (size_t)NCELLS * 2;
    rec_out[1] = rec_out[0] + (size_t)NCELLS * 2000;

    // scratch pointers
    float *hb, *accb, *xb, *t1b, *cvb, *fwb;
    int *rpb, *cntb, *wob, *ccb;
    cudaGetSymbolAddress((void**)&hb,   g_h);
    cudaGetSymbolAddress((void**)&accb, g_acc);
    cudaGetSymbolAddress((void**)&xb,   g_x);
    cudaGetSymbolAddress((void**)&t1b,  g_t1);
    cudaGetSymbolAddress((void**)&rpb,  g_rowptr);
    cudaGetSymbolAddress((void**)&cntb, g_cnt);
    cudaGetSymbolAddress((void**)&wob,  g_woff);
    cudaGetSymbolAddress((void**)&ccb,  g_ccol);
    cudaGetSymbolAddress((void**)&cvb,  g_cval);
    cudaGetSymbolAddress((void**)&fwb,  g_fw);

    // ---- CSR build for both hypergraph orders ----
    zero_int_kernel<<<(2 * NCELLS + 255) / 256, 256>>>(cntb, 2 * NCELLS);
    for (int o = 0; o < 2; o++) {
        int* cnt  = cntb + o * NCELLS;
        int* rp   = rpb + o * (NCELLS + 1);
        int* wo   = wob + o * NCELLS;
        int* cc   = ccb + o * EDGES;
        float* cv = cvb + o * EDGES;
        hist_kernel<<<(E + 255) / 256, 256>>>(row[o], E, cnt);
        scan_kernel<<<1, 1024>>>(cnt, rp, NCELLS);
        copy_int_kernel<<<(NCELLS + 255) / 256, 256>>>(rp, wo, NCELLS);
        scatter_kernel<<<(E + 255) / 256, 256>>>(row[o], col[o], val[o], E, wo, cc, cv);
    }
    softmax_fw_kernel<<<1, 32>>>(fWl[0], fWl[1], fwb);

    // ---- input projections: h[m][o] = X[m] @ Wi[m][o] + bi[m][o] ----
    for (int m = 0; m < 2; m++)
        for (int o = 0; o < 2; o++) {
            float* h = hb + (size_t)(m * 2 + o) * NCELLS * HID;
            launch_gemm(NCELLS, HID, D[m], X[m], D[m],
                        Wi[m] + (size_t)o * D[m] * HID, HID,
                        bi[m] + o * HID, h, HID, 0);
        }

    // ---- K-hop propagation per (modality, order) chain ----
    for (int m = 0; m < 2; m++)
        for (int o = 0; o < 2; o++) {
            const float* h  = hb + (size_t)(m * 2 + o) * NCELLS * HID;
            float* accp     = accb + (size_t)m * NCELLS * 2 * HID + o * HID;
            const float* fw = fwb + (m * 2 + o) * 11;
            const int* rp   = rpb + o * (NCELLS + 1);
            const int* cc   = ccb + o * EDGES;
            const float* cv = cvb + o * EDGES;

            init_acc_kernel<<<NCELLS, 256>>>(h, accp, 2 * HID, fw);
            const float* xc = h;
            float* xa = xb;
            float* xo2 = xb + (size_t)NCELLS * HID;
            for (int k = 1; k <= 10; k++) {
                spmm_csr_kernel<<<NCELLS, 256>>>(rp, cc, cv, xc, xa, accp, 2 * HID, fw + k);
                xc = xa;
                float* tmp = xa; xa = xo2; xo2 = tmp;
            }
        }

    // ---- output mixes: z_mod = acc @ Wo + bo (written straight into d_out) ----
    for (int m = 0; m < 2; m++) {
        const float* accp = accb + (size_t)m * NCELLS * 2 * HID;
        launch_gemm(NCELLS, HID, 2 * HID, accp, 2 * HID, Wo[m], HID, bo[m],
                    zmod_out[m], HID, 0);
    }

    // ---- attention fusion ----
    fuse_kernel<<<NCELLS, 256>>>(zmod_out[0], zmod_out[1], Wa, ba, z_out, w_out);

    // ---- decoders ----
    for (int m = 0; m < 2; m++) {
        launch_gemm(NCELLS, HID, HID, z_out, HID, Wd1[m], HID, bd1[m], t1b, HID, 1);
        launch_gemm(NCELLS, D[m], HID, t1b, HID, Wd2[m], D[m], bd2[m], rec_out[m], D[m], 0);
    }
}

// round 3
// speedup vs baseline: 2.2737x; 1.0803x over previous
#include <cuda_runtime.h>
#include <math.h>
#include <stdint.h>

#define NCELLS 10000
#define EDGES  320000
#define HID    256

// ---------------- scratch (static device globals; no allocation allowed) ----
__device__ float g_h2[2 * NCELLS * 512];           // per-order [N,512] (m0|m1 cols)
__device__ float g_acc[2 * NCELLS * 512];          // per-modality [N,512] (o0|o1 cols)
__device__ float g_x[2 * NCELLS * 512];            // ping-pong propagation buffers
__device__ float g_t1[NCELLS * 512];               // fused decoder hidden [N,512]
__device__ float g_xr[20000000];                   // pre-rounded X_rna
__device__ float g_xa[50000000];                   // pre-rounded X_atac
__device__ float g_wr[5769216];                    // pre-rounded weights (8 segments)
__device__ int   g_rowptr[2 * (NCELLS + 1)];
__device__ int   g_cnt[2 * NCELLS];
__device__ int   g_woff[2 * NCELLS];
__device__ int   g_ccol[2 * EDGES];
__device__ float g_cval[2 * EDGES];
__device__ float g_fw[4 * 11];

// weight-scratch segment offsets (floats)
#define OFF_WI_R   0
#define OFF_WI_A   1024000
#define OFF_WO_R   3584000
#define OFF_WO_A   3715072
#define OFF_WD1_R  3846144
#define OFF_WD1_A  3911680
#define OFF_WD2_R  3977216
#define OFF_WD2_A  4489216
#define W_TOTAL    5769216

__device__ __forceinline__ uint32_t f2tf32(float x) {
    uint32_t r;
    asm("cvt.rna.tf32.f32 %0, %1;" : "=r"(r) : "f"(x));
    return r;
}
__device__ __forceinline__ float roundtf(float x) {
    return __uint_as_float(f2tf32(x));
}

// ---------------- small utility kernels ------------------------------------
__global__ void zero_int_kernel(int* p, int n) {
    int i = blockIdx.x * blockDim.x + threadIdx.x;
    if (i < n) p[i] = 0;
}

__global__ void hist_kernel(const int* __restrict__ row, int e, int* cnt) {
    int i = blockIdx.x * blockDim.x + threadIdx.x;
    if (i < e) atomicAdd(&cnt[row[i]], 1);
}

__global__ void scan_kernel(const int* __restrict__ cnt, int* rowptr, int n) {
    __shared__ int buf[1024];
    __shared__ int carry;
    if (threadIdx.x == 0) { carry = 0; rowptr[0] = 0; }
    __syncthreads();
    for (int base = 0; base < n; base += 1024) {
        int i = base + threadIdx.x;
        int v = (i < n) ? cnt[i] : 0;
        buf[threadIdx.x] = v;
        __syncthreads();
        for (int off = 1; off < 1024; off <<= 1) {
            int t = 0;
            if (threadIdx.x >= off) t = buf[threadIdx.x - off];
            __syncthreads();
            if (threadIdx.x >= off) buf[threadIdx.x] += t;
            __syncthreads();
        }
        if (i < n) rowptr[i + 1] = carry + buf[threadIdx.x];
        __syncthreads();
        if (threadIdx.x == 0) carry += buf[1023];
        __syncthreads();
    }
}

__global__ void copy_int_kernel(const int* __restrict__ a, int* b, int n) {
    int i = blockIdx.x * blockDim.x + threadIdx.x;
    if (i < n) b[i] = a[i];
}

__global__ void scatter_kernel(const int* __restrict__ row, const int* __restrict__ col,
                               const float* __restrict__ val, int e,
                               int* woff, int* ccol, float* cval) {
    int i = blockIdx.x * blockDim.x + threadIdx.x;
    if (i < e) {
        int r = row[i];
        int p = atomicAdd(&woff[r], 1);
        ccol[p] = col[i];
        cval[p] = val[i];
    }
}

__global__ void softmax_fw_kernel(const float* __restrict__ fW_rna,
                                  const float* __restrict__ fW_atac,
                                  float* __restrict__ fw_out) {
    int id = threadIdx.x;
    if (id >= 4) return;
    const float* src = (id < 2) ? (fW_rna + id * 11) : (fW_atac + (id - 2) * 11);
    float m = -1e30f;
    for (int k = 0; k < 11; k++) m = fmaxf(m, src[k]);
    float e[11], s = 0.f;
    for (int k = 0; k < 11; k++) { e[k] = expf(src[k] - m); s += e[k]; }
    float inv = 1.f / s;
    for (int k = 0; k < 11; k++) fw_out[id * 11 + k] = e[k] * inv;
}

// pre-round both X matrices to tf32 (float4 granularity)
__global__ void preround_x_kernel(const float* __restrict__ xr, const float* __restrict__ xa,
                                  float* __restrict__ dxr, float* __restrict__ dxa) {
    const size_t NR4 = 20000000 / 4, NA4 = 50000000 / 4;
    size_t i = (size_t)blockIdx.x * blockDim.x + threadIdx.x;
    if (i < NR4) {
        float4 v = ((const float4*)xr)[i];
        v.x = roundtf(v.x); v.y = roundtf(v.y); v.z = roundtf(v.z); v.w = roundtf(v.w);
        ((float4*)dxr)[i] = v;
    } else if (i < NR4 + NA4) {
        size_t j = i - NR4;
        float4 v = ((const float4*)xa)[j];
        v.x = roundtf(v.x); v.y = roundtf(v.y); v.z = roundtf(v.z); v.w = roundtf(v.w);
        ((float4*)dxa)[j] = v;
    }
}

// pre-round the 8 weight segments into g_wr
__global__ void preround_w_kernel(const float* s0, const float* s1, const float* s2,
                                  const float* s3, const float* s4, const float* s5,
                                  const float* s6, const float* s7, float* dst) {
    size_t i4 = (size_t)blockIdx.x * blockDim.x + threadIdx.x;
    size_t i = i4 * 4;
    if (i >= W_TOTAL) return;
    const float* src;
    size_t off;
    if      (i < OFF_WI_A)  { src = s0; off = i - OFF_WI_R; }
    else if (i < OFF_WO_R)  { src = s1; off = i - OFF_WI_A; }
    else if (i < OFF_WO_A)  { src = s2; off = i - OFF_WO_R; }
    else if (i < OFF_WD1_R) { src = s3; off = i - OFF_WO_A; }
    else if (i < OFF_WD1_A) { src = s4; off = i - OFF_WD1_R; }
    else if (i < OFF_WD2_R) { src = s5; off = i - OFF_WD1_A; }
    else if (i < OFF_WD2_A) { src = s6; off = i - OFF_WD2_R; }
    else                    { src = s7; off = i - OFF_WD2_A; }
    float4 v = *(const float4*)(src + off);
    v.x = roundtf(v.x); v.y = roundtf(v.y); v.z = roundtf(v.z); v.w = roundtf(v.w);
    *(float4*)(dst + i) = v;
}

// fused dual-modality CSR spmm, 512 threads: cols [0,256)=rna, [256,512)=atac
__global__ void spmm2_kernel(const int* __restrict__ rowptr,
                             const int* __restrict__ cols,
                             const float* __restrict__ vals,
                             const float* __restrict__ x,
                             float* __restrict__ y,
                             float* __restrict__ acc0, float* __restrict__ acc1,
                             int oOff, const float* __restrict__ fw,
                             int k, int last) {
    int r = blockIdx.x;
    int t = threadIdx.x;
    int m = t >> 8;
    int tt = t & 255;
    int ci = m * 2 + (oOff >> 8);
    int s = rowptr[r], e = rowptr[r + 1];
    float sum = 0.f;
    int i = s;
    for (; i + 1 < e; i += 2) {
        int   c0 = __ldg(&cols[i]);
        int   c1 = __ldg(&cols[i + 1]);
        float v0 = __ldg(&vals[i]);
        float v1 = __ldg(&vals[i + 1]);
        float x0 = __ldg(&x[(size_t)c0 * 512 + t]);
        float x1 = __ldg(&x[(size_t)c1 * 512 + t]);
        sum += v0 * x0;
        sum += v1 * x1;
    }
    if (i < e) {
        int c = __ldg(&cols[i]);
        sum += __ldg(&vals[i]) * __ldg(&x[(size_t)c * 512 + t]);
    }
    if (!last) y[(size_t)r * 512 + t] = sum;
    float w = __ldg(&fw[ci * 11 + k]);
    float* accm = m ? acc1 : acc0;
    size_t ai = (size_t)r * 512 + oOff + tt;
    if (k == 1) {
        float w0 = __ldg(&fw[ci * 11]);
        accm[ai] = w0 * x[(size_t)r * 512 + t] + w * sum;
    } else {
        accm[ai] += w * sum;
    }
}

// attention fusion
__global__ void fuse_kernel(const float* __restrict__ z_rna, const float* __restrict__ z_atac,
                            const float* __restrict__ Wa, const float* __restrict__ ba,
                            float* __restrict__ z, float* __restrict__ weight) {
    int n = blockIdx.x, t = threadIdx.x;
    float zr = z_rna[(size_t)n * HID + t];
    float za = z_atac[(size_t)n * HID + t];
    float p0 = zr * Wa[t * 2 + 0] + za * Wa[(HID + t) * 2 + 0];
    float p1 = zr * Wa[t * 2 + 1] + za * Wa[(HID + t) * 2 + 1];
    __shared__ float s0[256], s1[256];
    s0[t] = p0; s1[t] = p1;
    __syncthreads();
    for (int off = 128; off > 0; off >>= 1) {
        if (t < off) { s0[t] += s0[t + off]; s1[t] += s1[t + off]; }
        __syncthreads();
    }
    __shared__ float w0s, w1s;
    if (t == 0) {
        float a0 = s0[0] + ba[0];
        float a1 = s1[0] + ba[1];
        float m = fmaxf(a0, a1);
        float e0 = expf(a0 - m), e1 = expf(a1 - m);
        float inv = 1.f / (e0 + e1);
        w0s = e0 * inv; w1s = e1 * inv;
        weight[n * 2 + 0] = w0s;
        weight[n * 2 + 1] = w1s;
    }
    __syncthreads();
    z[(size_t)n * HID + t] = w0s * zr + w1s * za;
}

// ---------------- TF32 tensor-core GEMM (split-B/C, 3-stage cp.async) -------
__device__ __forceinline__ void mma_tf32(float* d, const uint32_t* a, const uint32_t* b) {
    asm volatile(
        "mma.sync.aligned.m16n8k8.row.col.f32.tf32.tf32.f32 "
        "{%0,%1,%2,%3}, {%4,%5,%6,%7}, {%8,%9}, {%0,%1,%2,%3};"
        : "+f"(d[0]), "+f"(d[1]), "+f"(d[2]), "+f"(d[3])
        : "r"(a[0]), "r"(a[1]), "r"(a[2]), "r"(a[3]), "r"(b[0]), "r"(b[1]));
}

__device__ __forceinline__ void cpasync16(uint32_t dst, const void* src, int srcBytes) {
    asm volatile("cp.async.ca.shared.global [%0], [%1], 16, %2;"
                 :: "r"(dst), "l"(src), "r"(srcBytes));
}

#define GEMM_SMEM (3 * (128 * 20 + 16 * 136) * 4)

template <int CVTA, int CVTB>
__global__ __launch_bounds__(256, 2)
void gemm_k(int M, int N, int K,
            const float* __restrict__ A, int lda,
            const float* __restrict__ B1, const float* __restrict__ B2, int ldb,
            int nSplit,
            const float* __restrict__ bias1, const float* __restrict__ bias2,
            float* __restrict__ C1, float* __restrict__ C2, int ldc, int relu) {
    extern __shared__ float smem[];
    float (*As)[128][20] = (float(*)[128][20])smem;                 // 3 stages
    float (*Bs)[16][136] = (float(*)[16][136])(smem + 3 * 128 * 20);

    const int tid  = threadIdx.x;
    const int wid  = tid >> 5;
    const int lane = tid & 31;
    const int wm   = (wid >> 2) * 64;
    const int wn   = (wid & 3) * 32;
    const int r    = lane >> 2;
    const int c    = lane & 3;
    const int mBase = blockIdx.y * 128;
    const int nBase = blockIdx.x * 128;

    const bool hi = (nBase >= nSplit);
    const float* B    = hi ? B2 : B1;
    const float* bias = hi ? bias2 : bias1;
    float*       C    = hi ? C2 : C1;
    const int nOff = nBase - (hi ? nSplit : 0);
    const int Nb   = hi ? (N - nSplit) : (N < nSplit ? N : nSplit);

    float acc[4][4][4];
#pragma unroll
    for (int i = 0; i < 4; i++)
#pragma unroll
        for (int j = 0; j < 4; j++)
#pragma unroll
            for (int q = 0; q < 4; q++) acc[i][j][q] = 0.f;

    const int NT = (K + 15) / 16;

    auto load_stage = [&](int st, int k0) {
#pragma unroll
        for (int i = 0; i < 2; i++) {
            int ch = tid + i * 256;
            int m  = ch >> 2;
            int k4 = (ch & 3) << 2;
            const float* src = A + (size_t)(mBase + m) * lda + (k0 + k4);
            int sz = ((mBase + m) < M && (k0 + k4) < K) ? 16 : 0;
            cpasync16((uint32_t)__cvta_generic_to_shared(&As[st][m][k4]), src, sz);
        }
#pragma unroll
        for (int i = 0; i < 2; i++) {
            int ch = tid + i * 256;
            int k  = ch >> 5;
            int nc = (ch & 31) << 2;
            const float* src = B + (size_t)(k0 + k) * ldb + (nOff + nc);
            int sz = ((k0 + k) < K && (nOff + nc) < Nb) ? 16 : 0;
            cpasync16((uint32_t)__cvta_generic_to_shared(&Bs[st][k][nc]), src, sz);
        }
        asm volatile("cp.async.commit_group;");
    };

    load_stage(0, 0);
    if (NT > 1) load_stage(1, 16);
    else        asm volatile("cp.async.commit_group;");  // keep group count sane

    int st = 0;
    for (int t = 0; t < NT; ++t) {
        __syncthreads();   // everyone done with the stage about to be overwritten
        if (t + 2 < NT) {
            int ls = st + 2; if (ls >= 3) ls -= 3;
            load_stage(ls, (t + 2) * 16);
            asm volatile("cp.async.wait_group 2;");
        } else if (t + 1 < NT) {
            asm volatile("cp.async.wait_group 1;");
        } else {
            asm volatile("cp.async.wait_group 0;");
        }
        __syncthreads();

#pragma unroll
        for (int s = 0; s < 2; ++s) {
            const int kk = s * 8;
            uint32_t af[4][4], bf[4][2];
#pragma unroll
            for (int mt = 0; mt < 4; mt++) {
                int m = wm + mt * 16;
                if (CVTA) {
                    af[mt][0] = f2tf32(As[st][m + r    ][kk + c    ]);
                    af[mt][1] = f2tf32(As[st][m + r + 8][kk + c    ]);
                    af[mt][2] = f2tf32(As[st][m + r    ][kk + c + 4]);
                    af[mt][3] = f2tf32(As[st][m + r + 8][kk + c + 4]);
                } else {
                    af[mt][0] = __float_as_uint(As[st][m + r    ][kk + c    ]);
                    af[mt][1] = __float_as_uint(As[st][m + r + 8][kk + c    ]);
                    af[mt][2] = __float_as_uint(As[st][m + r    ][kk + c + 4]);
                    af[mt][3] = __float_as_uint(As[st][m + r + 8][kk + c + 4]);
                }
            }
#pragma unroll
            for (int nt = 0; nt < 4; nt++) {
                int n = wn + nt * 8;
                if (CVTB) {
                    bf[nt][0] = f2tf32(Bs[st][kk + c    ][n + r]);
                    bf[nt][1] = f2tf32(Bs[st][kk + c + 4][n + r]);
                } else {
                    bf[nt][0] = __float_as_uint(Bs[st][kk + c    ][n + r]);
                    bf[nt][1] = __float_as_uint(Bs[st][kk + c + 4][n + r]);
                }
            }
#pragma unroll
            for (int mt = 0; mt < 4; mt++)
#pragma unroll
                for (int nt = 0; nt < 4; nt++)
                    mma_tf32(acc[mt][nt], af[mt], bf[nt]);
        }
        st++; if (st >= 3) st -= 3;
    }

#pragma unroll
    for (int mt = 0; mt < 4; mt++) {
        int row0 = mBase + wm + mt * 16 + r;
#pragma unroll
        for (int nt = 0; nt < 4; nt++) {
            int col = nOff + wn + nt * 8 + 2 * c;
            if (col < Nb) {
                float b0v = bias[col], b1v = bias[col + 1];
                if (row0 < M) {
                    float v0 = acc[mt][nt][0] + b0v;
                    float v1 = acc[mt][nt][1] + b1v;
                    if (relu) { v0 = fmaxf(v0, 0.f); v1 = fmaxf(v1, 0.f); }
                    *(float2*)&C[(size_t)row0 * ldc + col] = make_float2(v0, v1);
                }
                int row1 = row0 + 8;
                if (row1 < M) {
                    float v0 = acc[mt][nt][2] + b0v;
                    float v1 = acc[mt][nt][3] + b1v;
                    if (relu) { v0 = fmaxf(v0, 0.f); v1 = fmaxf(v1, 0.f); }
                    *(float2*)&C[(size_t)row1 * ldc + col] = make_float2(v0, v1);
                }
            }
        }
    }
}

// ---------------- host side -------------------------------------------------
#define NSPLIT_NONE (1 << 30)

static inline void launch_gemm_nc(int M, int N, int K,
                                  const float* A, int lda,
                                  const float* B1, const float* B2, int ldb, int nSplit,
                                  const float* bias1, const float* bias2,
                                  float* C1, float* C2, int ldc, int relu) {
    dim3 grid((N + 127) / 128, (M + 127) / 128);
    cudaFuncSetAttribute(gemm_k<0, 0>, cudaFuncAttributeMaxDynamicSharedMemorySize, GEMM_SMEM);
    gemm_k<0, 0><<<grid, 256, GEMM_SMEM>>>(M, N, K, A, lda, B1, B2, ldb, nSplit,
                                           bias1, bias2, C1, C2, ldc, relu);
}

static inline void launch_gemm_cv(int M, int N, int K,
                                  const float* A, int lda,
                                  const float* B1, const float* B2, int ldb, int nSplit,
                                  const float* bias1, const float* bias2,
                                  float* C1, float* C2, int ldc, int relu) {
    dim3 grid((N + 127) / 128, (M + 127) / 128);
    cudaFuncSetAttribute(gemm_k<1, 0>, cudaFuncAttributeMaxDynamicSharedMemorySize, GEMM_SMEM);
    gemm_k<1, 0><<<grid, 256, GEMM_SMEM>>>(M, N, K, A, lda, B1, B2, ldb, nSplit,
                                           bias1, bias2, C1, C2, ldc, relu);
}

extern "C" void kernel_launch(void* const* d_in, const int* in_sizes, int n_in,
                              void* d_out, int out_size) {
    (void)n_in; (void)out_size;
    const float* X[2]   = {(const float*)d_in[0], (const float*)d_in[1]};
    const int*   row[2] = {(const int*)d_in[2], (const int*)d_in[5]};
    const int*   col[2] = {(const int*)d_in[3], (const int*)d_in[6]};
    const float* val[2] = {(const float*)d_in[4], (const float*)d_in[7]};
    const float* Wi[2]  = {(const float*)d_in[8],  (const float*)d_in[13]};
    const float* bi[2]  = {(const float*)d_in[9],  (const float*)d_in[14]};
    const float* fWl[2] = {(const float*)d_in[10], (const float*)d_in[15]};
    const float* Wo[2]  = {(const float*)d_in[11], (const float*)d_in[16]};
    const float* bo[2]  = {(const float*)d_in[12], (const float*)d_in[17]};
    const float* Wa     = (const float*)d_in[18];
    const float* ba     = (const float*)d_in[19];
    const float* Wd1[2] = {(const float*)d_in[20], (const float*)d_in[24]};
    const float* bd1[2] = {(const float*)d_in[21], (const float*)d_in[25]};
    const float* Wd2[2] = {(const float*)d_in[22], (const float*)d_in[26]};
    const float* bd2[2] = {(const float*)d_in[23], (const float*)d_in[27]};
    const int D[2] = {2000, 5000};
    const int E = in_sizes[2];

    float* out = (float*)d_out;
    float* z_out       = out;
    float* zmod_out[2] = {out + (size_t)NCELLS * HID, out + 2 * (size_t)NCELLS * HID};
    float* w_out       = out + 3 * (size_t)NCELLS * HID;
    float* rec_out[2];
    rec_out[0] = w_out + (size_t)NCELLS * 2;
    rec_out[1] = rec_out[0] + (size_t)NCELLS * 2000;

    float *h2b, *accb, *xb, *t1b, *cvb, *fwb, *xrb, *xab, *wrb;
    int *rpb, *cntb, *wob, *ccb;
    cudaGetSymbolAddress((void**)&h2b,  g_h2);
    cudaGetSymbolAddress((void**)&accb, g_acc);
    cudaGetSymbolAddress((void**)&xb,   g_x);
    cudaGetSymbolAddress((void**)&t1b,  g_t1);
    cudaGetSymbolAddress((void**)&xrb,  g_xr);
    cudaGetSymbolAddress((void**)&xab,  g_xa);
    cudaGetSymbolAddress((void**)&wrb,  g_wr);
    cudaGetSymbolAddress((void**)&rpb,  g_rowptr);
    cudaGetSymbolAddress((void**)&cntb, g_cnt);
    cudaGetSymbolAddress((void**)&wob,  g_woff);
    cudaGetSymbolAddress((void**)&ccb,  g_ccol);
    cudaGetSymbolAddress((void**)&cvb,  g_cval);
    cudaGetSymbolAddress((void**)&fwb,  g_fw);

    // 1) fW softmax
    softmax_fw_kernel<<<1, 32>>>(fWl[0], fWl[1], fwb);
    // 2) pre-round weights
    {
        int n4 = (W_TOTAL / 4 + 255) / 256;
        preround_w_kernel<<<n4, 256>>>(Wi[0], Wi[1], Wo[0], Wo[1],
                                       Wd1[0], Wd1[1], Wd2[0], Wd2[1], wrb);
    }
    // 3) pre-round X
    {
        size_t tot4 = (20000000ull + 50000000ull) / 4;
        preround_x_kernel<<<(unsigned)((tot4 + 255) / 256), 256>>>(X[0], X[1], xrb, xab);
    }
    // 4) CSR count zero
    zero_int_kernel<<<(2 * NCELLS + 255) / 256, 256>>>(cntb, 2 * NCELLS);

    // 5-6) fused input projections (order-fused, N=512): h2[o][n][m*256+j]
    const float* Apr[2]  = {xrb, xab};
    const float* WiPr[2] = {wrb + OFF_WI_R, wrb + OFF_WI_A};
    for (int m = 0; m < 2; m++) {
        launch_gemm_nc(NCELLS, 512, D[m], Apr[m], D[m],
                       WiPr[m], WiPr[m] + (size_t)D[m] * HID, HID, 256,
                       bi[m], bi[m] + HID,
                       h2b + m * HID, h2b + (size_t)NCELLS * 512 + m * HID, 512, 0);
    }

    // CSR build
    for (int o = 0; o < 2; o++) {
        int* cnt  = cntb + o * NCELLS;
        int* rp   = rpb + o * (NCELLS + 1);
        int* wo   = wob + o * NCELLS;
        int* cc   = ccb + o * EDGES;
        float* cv = cvb + o * EDGES;
        hist_kernel<<<(E + 255) / 256, 256>>>(row[o], E, cnt);
        scan_kernel<<<1, 1024>>>(cnt, rp, NCELLS);
        copy_int_kernel<<<(NCELLS + 255) / 256, 256>>>(rp, wo, NCELLS);
        scatter_kernel<<<(E + 255) / 256, 256>>>(row[o], col[o], val[o], E, wo, cc, cv);
    }

    // K-hop propagation, fused over modalities (per order o)
    float* acc0 = accb;
    float* acc1 = accb + (size_t)NCELLS * 512;
    for (int o = 0; o < 2; o++) {
        const int* rp   = rpb + o * (NCELLS + 1);
        const int* cc   = ccb + o * EDGES;
        const float* cv = cvb + o * EDGES;
        const float* xc = h2b + (size_t)o * NCELLS * 512;
        float* ya  = xb;
        float* yb2 = xb + (size_t)NCELLS * 512;
        for (int k = 1; k <= 10; k++) {
            spmm2_kernel<<<NCELLS, 512>>>(rp, cc, cv, xc, ya, acc0, acc1,
                                          o * 256, fwb, k, k == 10);
            xc = ya;
            float* tmp = ya; ya = yb2; yb2 = tmp;
        }
    }

    // output mixes: z_mod = acc_m @ Wo_m + bo_m
    for (int m = 0; m < 2; m++) {
        const float* accp = (m ? acc1 : acc0);
        launch_gemm_cv(NCELLS, HID, 2 * HID, accp, 512,
                       wrb + (m ? OFF_WO_A : OFF_WO_R), wrb, HID, NSPLIT_NONE,
                       bo[m], bo[m], zmod_out[m], zmod_out[m], HID, 0);
    }

    // attention fusion
    fuse_kernel<<<NCELLS, 256>>>(zmod_out[0], zmod_out[1], Wa, ba, z_out, w_out);

    // decoders: fused hidden GEMM (A=z shared), then per-modality output GEMM
    launch_gemm_cv(NCELLS, 512, HID, z_out, HID,
                   wrb + OFF_WD1_R, wrb + OFF_WD1_A, 256, 256,
                   bd1[0], bd1[1], t1b, t1b + 256, 512, 1);
    for (int m = 0; m < 2; m++) {
        launch_gemm_cv(NCELLS, D[m], HID, t1b + m * HID, 512,
                       wrb + (m ? OFF_WD2_A : OFF_WD2_R), wrb, D[m], NSPLIT_NONE,
                       bd2[m], bd2[m], rec_out[m], rec_out[m], D[m], 0);
    }
}